// round 16
// baseline (speedup 1.0000x reference)
#include <cuda_runtime.h>
#include <cuda_fp16.h>
#include <math.h>
#include <stdint.h>

// ---------------------------------------------------------------------------
// Problem: B=4, T=1024, C=1024, H=16, Dh=64, D_FF=4096, WINDOW=256. M=4096.
// ---------------------------------------------------------------------------
#define TOKENS 4096
#define CDIM   1024
#define FFDIM  4096
#define WIN    256

__device__ float  g_y[TOKENS * CDIM];
__device__ float  g_x1[TOKENS * CDIM];         // exact (residual)
__device__ __half g_qkvh[TOKENS * 3 * CDIM];   // fp16 qkv
__device__ __half g_xh[TOKENS * CDIM];
__device__ __half g_ctxh[TOKENS * CDIM];
__device__ __half g_x1h[TOKENS * CDIM];
__device__ __half g_hh[TOKENS * FFDIM];
__device__ __half g_wqkvh[3 * CDIM * CDIM];
__device__ __half g_woh[CDIM * CDIM];
__device__ __half g_w1h[FFDIM * CDIM];
__device__ __half g_w2h[CDIM * FFDIM];

// ---------------------------------------------------------------------------
// helpers
// ---------------------------------------------------------------------------
__device__ __forceinline__ uint32_t smem_u32(const void* p) {
    uint32_t a;
    asm("{ .reg .u64 t; cvta.to.shared.u64 t, %1; cvt.u32.u64 %0, t; }"
        : "=r"(a) : "l"(p));
    return a;
}

#define CP_ASYNC16(sa, ga) \
    asm volatile("cp.async.cg.shared.global [%0], [%1], 16;" :: "r"((uint32_t)(sa)), "l"(ga))
#define CP_COMMIT() asm volatile("cp.async.commit_group;" ::: "memory")
#define CP_WAIT(n)  asm volatile("cp.async.wait_group %0;" :: "n"(n) : "memory")

#define LDSM4(R0, R1, R2, R3, ADDR) \
    asm volatile("ldmatrix.sync.aligned.m8n8.x4.shared.b16 {%0,%1,%2,%3}, [%4];" \
        : "=r"(R0), "=r"(R1), "=r"(R2), "=r"(R3) : "r"(ADDR))

__device__ __forceinline__ void mma_f16(float* d, const uint32_t* a,
                                        uint32_t b0, uint32_t b1) {
    asm volatile(
        "mma.sync.aligned.m16n8k16.row.col.f32.f16.f16.f32 "
        "{%0,%1,%2,%3}, {%4,%5,%6,%7}, {%8,%9}, {%0,%1,%2,%3};"
        : "+f"(d[0]), "+f"(d[1]), "+f"(d[2]), "+f"(d[3])
        : "r"(a[0]), "r"(a[1]), "r"(a[2]), "r"(a[3]), "r"(b0), "r"(b1));
}

__device__ __forceinline__ float gelu_exact(float v) {
    return 0.5f * v * (1.0f + erff(v * 0.70710678118654752f));
}

// ---------------------------------------------------------------------------
// fused fp32 -> fp16 conversion pass over 5 buffers (sizes in float4 units)
// ---------------------------------------------------------------------------
__global__ void __launch_bounds__(256) cvt_all_kernel(
    const float4* __restrict__ i0, __half2* __restrict__ o0, int n0,
    const float4* __restrict__ i1, __half2* __restrict__ o1, int n1,
    const float4* __restrict__ i2, __half2* __restrict__ o2, int n2,
    const float4* __restrict__ i3, __half2* __restrict__ o3, int n3,
    const float4* __restrict__ i4, __half2* __restrict__ o4, int n4)
{
    const int total = n0 + n1 + n2 + n3 + n4;
    const int stride = gridDim.x * 256;
    for (int i = blockIdx.x * 256 + threadIdx.x; i < total; i += stride) {
        const float4* src;
        __half2* dst;
        int idx = i;
        if (idx < n0)                    { src = i0; dst = o0; }
        else if ((idx -= n0) < n1)       { src = i1; dst = o1; }
        else if ((idx -= n1) < n2)       { src = i2; dst = o2; }
        else if ((idx -= n2) < n3)       { src = i3; dst = o3; }
        else            { idx -= n3;       src = i4; dst = o4; }
        float4 v = src[idx];
        dst[2 * idx + 0] = __floats2half2_rn(v.x, v.y);
        dst[2 * idx + 1] = __floats2half2_rn(v.z, v.w);
    }
}

// ---------------------------------------------------------------------------
// fp16 mma.sync GEMM: C[m,n] = sum_k A[m,k]*B[n,k] + bias (+resid)(+gelu)
// R16: CTA 128x256xBK64, 8 warps (2m x 4n), warp tile 64x64, 256 threads.
// GEMM is smem-crossbar bound (~83% of chunk time at warp tile 32x64 =
// 192 B/MMA). 64x64 warp tile cuts this to 128 B/MMA while keeping 8 warps
// for latency cover (R14 failed with only 4). 110.6KB smem -> 1 CTA/SM.
// Proven R10/R11 2-stage loop.
// ---------------------------------------------------------------------------
#define GBM 128
#define GBN 256
#define GBK 64
#define HSTR 72
#define HSTG ((GBM + GBN) * HSTR)          // 27648 halfs / stage
#define GEMM_SMEM (2 * HSTG * 2)           // 110592 bytes

template <bool GELU, bool RESID, bool OUTH, int KDIM>
__global__ void __launch_bounds__(256, 1) hgemm(
    const __half* __restrict__ A, const __half* __restrict__ B,
    const float* __restrict__ bias, const float* __restrict__ resid,
    void* __restrict__ Cv, int N)
{
    extern __shared__ __half smh[];
    const int tid  = threadIdx.x;
    const int wid  = tid >> 5, lane = tid & 31;
    const int wm   = wid >> 2, wn = wid & 3;     // 2m x 4n warp grid
    const int g    = lane >> 2, tg = lane & 3;
    const int m0   = blockIdx.y * GBM;
    const int n0   = blockIdx.x * GBN;
    constexpr int NITER = KDIM / GBK;
    static_assert(NITER % 2 == 0, "NITER even");

    float acc[4][8][4];
    #pragma unroll
    for (int i = 0; i < 4; i++)
        #pragma unroll
        for (int j = 0; j < 8; j++)
            #pragma unroll
            for (int k = 0; k < 4; k++) acc[i][j][k] = 0.f;

    // loader lanes: 256 threads; A 128 rows (4 iters of 32), B 256 rows (8)
    const int lr = tid >> 3;            // 0..31
    const int ls = (tid & 7) * 8;       // half offset 0..56
    const __half* aptr = A + (size_t)(m0 + lr) * KDIM + ls;
    const __half* bptr = B + (size_t)(n0 + lr) * KDIM + ls;
    const uint32_t sa_st = smem_u32(smh) + (uint32_t)(lr * HSTR + ls) * 2u;
    const uint32_t sb_st = sa_st + GBM * HSTR * 2u;
    constexpr uint32_t STGB = HSTG * 2u;

    auto load_chunk = [&](uint32_t stoff) {
        #pragma unroll
        for (int i = 0; i < 4; i++)
            CP_ASYNC16(sa_st + stoff + i * (32 * HSTR * 2),
                       aptr + (size_t)i * 32 * KDIM);
        #pragma unroll
        for (int i = 0; i < 8; i++)
            CP_ASYNC16(sb_st + stoff + i * (32 * HSTR * 2),
                       bptr + (size_t)i * 32 * KDIM);
        aptr += GBK; bptr += GBK;
    };

    const uint32_t smb = smem_u32(smh);
    const int m_a = wm * 64 + ((lane >> 3) & 1) * 8 + (lane & 7);
    const uint32_t aAb = smb + (uint32_t)(m_a * HSTR + (lane >> 4) * 8) * 2u;
    const int n_b = wn * 64 + (lane >> 4) * 8 + (lane & 7);
    const uint32_t aBb = smb + (uint32_t)(GBM * HSTR + n_b * HSTR
                                          + ((lane >> 3) & 1) * 8) * 2u;

    auto compute = [&](uint32_t stoff) {
        #pragma unroll
        for (int kk = 0; kk < GBK / 16; kk++) {
            const uint32_t koff = stoff + kk * 32;
            uint32_t a[4][4];
            #pragma unroll
            for (int mi = 0; mi < 4; mi++)
                LDSM4(a[mi][0], a[mi][1], a[mi][2], a[mi][3],
                      aAb + koff + mi * (16 * HSTR * 2));
            #pragma unroll
            for (int p = 0; p < 4; p++) {
                uint32_t b0, b1, b2, b3;
                LDSM4(b0, b1, b2, b3, aBb + koff + p * (16 * HSTR * 2));
                #pragma unroll
                for (int mi = 0; mi < 4; mi++) {
                    mma_f16(acc[mi][2 * p],     a[mi], b0, b1);
                    mma_f16(acc[mi][2 * p + 1], a[mi], b2, b3);
                }
            }
        }
    };

    load_chunk(0); CP_COMMIT();

    #pragma unroll 1
    for (int j = 0; j < NITER; j += 2) {
        load_chunk(STGB); CP_COMMIT();
        CP_WAIT(1);
        __syncthreads();
        compute(0);
        __syncthreads();
        if (j + 2 < NITER) load_chunk(0);
        CP_COMMIT();
        CP_WAIT(1);
        __syncthreads();
        compute(STGB);
        __syncthreads();
    }

    // epilogue
    #pragma unroll
    for (int mi = 0; mi < 4; mi++) {
        #pragma unroll
        for (int rr = 0; rr < 2; rr++) {
            const int m = m0 + wm * 64 + mi * 16 + rr * 8 + g;
            const float* rrow = RESID ? (resid + (size_t)m * N) : nullptr;
            #pragma unroll
            for (int ni = 0; ni < 8; ni++) {
                const int n = n0 + wn * 64 + ni * 8 + 2 * tg;
                float ox = acc[mi][ni][rr * 2 + 0] + bias[n];
                float oy = acc[mi][ni][rr * 2 + 1] + bias[n + 1];
                if (RESID) { ox += rrow[n]; oy += rrow[n + 1]; }
                if (GELU)  { ox = gelu_exact(ox); oy = gelu_exact(oy); }
                if (OUTH) {
                    __half* crow = (__half*)Cv + (size_t)m * N;
                    *(__half2*)(crow + n) = __floats2half2_rn(ox, oy);
                } else {
                    float* crow = (float*)Cv + (size_t)m * N;
                    *(float2*)(crow + n) = make_float2(ox, oy);
                }
            }
        }
    }
}

// ---------------------------------------------------------------------------
// Banded causal attention, fp16 mma.sync, q-tile 128 (R15, best).
// ---------------------------------------------------------------------------
#define QT  128
#define APH 72
#define APS 81
#define ATTN_SMEM ((2 * QT + 2 * 64) * APH * 2 + (QT * APS + 3 * QT + 2 * QT) * 4)

__global__ void __launch_bounds__(256, 2) attn_kernel(
    const __half* __restrict__ qkv, __half* __restrict__ ctxh)
{
    extern __shared__ __half smh[];
    __half* Qh = smh;                       // 128 x APH
    __half* Kh = smh + QT * APH;            // 64 x APH
    __half* Vt = Kh + 64 * APH;             // 64 x APH  ([d][k])
    __half* Ph = Vt + 64 * APH;             // 128 x APH
    float* Ps    = (float*)(Ph + QT * APH); // 128 x APS
    float* row_m = Ps + QT * APS;
    float* row_l = row_m + QT;
    float* row_a = row_l + QT;
    float* red   = row_a + QT;              // 128 x 2

    const int t    = threadIdx.x;
    const int wid  = t >> 5, lane = t & 31;
    const int g    = lane >> 2, tg = lane & 3;
    const int wm   = wid >> 1, wn = wid & 1;
    const int m0   = wm * 32;
    const int n0   = wn * 32;
    const int bh   = blockIdx.y;
    const int b    = bh >> 4, h = bh & 15;
    const int q0   = blockIdx.x * QT;
    const size_t base = (size_t)b * 1024 * 3072 + (size_t)h * 64;
    const int i_row = t & 127, grp = t >> 7;

    {
        const int r = t >> 1, c = (t & 1) * 32;
        const __half2 sc = __floats2half2_rn(0.125f, 0.125f);
        #pragma unroll
        for (int cc = 0; cc < 32; cc += 8) {
            uint4 v = *(const uint4*)(qkv + base + (size_t)(q0 + r) * 3072 + c + cc);
            __half2* hv = (__half2*)&v;
            hv[0] = __hmul2(hv[0], sc); hv[1] = __hmul2(hv[1], sc);
            hv[2] = __hmul2(hv[2], sc); hv[3] = __hmul2(hv[3], sc);
            *(uint4*)&Qh[r * APH + c + cc] = v;
        }
    }
    if (t < QT) { row_m[t] = -1e30f; row_l[t] = 0.f; }

    float o[2][4][4];
    #pragma unroll
    for (int mf = 0; mf < 2; mf++)
        #pragma unroll
        for (int i = 0; i < 4; i++)
            #pragma unroll
            for (int j = 0; j < 4; j++) o[mf][i][j] = 0.f;

    const uint32_t smb = smem_u32(smh);
    const int m_a = m0 + ((lane >> 3) & 1) * 8 + (lane & 7);
    const uint32_t kofA = (lane >> 4) * 8;
    const uint32_t aQ = smb + (uint32_t)(m_a * APH + kofA) * 2u;
    const uint32_t aP = aQ + (uint32_t)((QT + 2 * 64) * APH) * 2u;
    const int n_b = n0 + (lane >> 4) * 8 + (lane & 7);
    const uint32_t kofB = ((lane >> 3) & 1) * 8;
    const uint32_t aK = smb + (uint32_t)(QT * APH + n_b * APH + kofB) * 2u;
    const uint32_t aV = aK + (uint32_t)(64 * APH) * 2u;

    const int kt_lo = (q0 >= WIN) ? ((q0 - (WIN - 1)) >> 6) : 0;
    const int kt_hi = (q0 + QT - 1) >> 6;

    const int lrow = t >> 2;
    const int lcol = (t & 3) * 16;

    for (int kt = kt_lo; kt <= kt_hi; kt++) {
        const int k0 = kt * 64;
        __syncthreads();
        {
            #pragma unroll
            for (int cc = 0; cc < 16; cc += 8) {
                uint4 kv = *(const uint4*)(qkv + base + (size_t)(k0 + lrow) * 3072 + 1024 + lcol + cc);
                *(uint4*)&Kh[lrow * APH + lcol + cc] = kv;
                uint4 vv = *(const uint4*)(qkv + base + (size_t)(k0 + lrow) * 3072 + 2048 + lcol + cc);
                const __half* hv = (const __half*)&vv;
                #pragma unroll
                for (int i = 0; i < 8; i++)
                    Vt[(lcol + cc + i) * APH + lrow] = hv[i];
            }
        }
        __syncthreads();

        float s4[2][4][4];
        #pragma unroll
        for (int mf = 0; mf < 2; mf++)
            #pragma unroll
            for (int i = 0; i < 4; i++)
                #pragma unroll
                for (int j = 0; j < 4; j++) s4[mf][i][j] = 0.f;
        #pragma unroll
        for (int kk = 0; kk < 4; kk++) {
            const uint32_t koff = kk * 32;
            uint32_t a0[4], a1[4];
            LDSM4(a0[0], a0[1], a0[2], a0[3], aQ + koff);
            LDSM4(a1[0], a1[1], a1[2], a1[3], aQ + koff + 16 * APH * 2);
            uint32_t b0, b1, b2, b3;
            LDSM4(b0, b1, b2, b3, aK + koff);
            mma_f16(s4[0][0], a0, b0, b1);
            mma_f16(s4[0][1], a0, b2, b3);
            mma_f16(s4[1][0], a1, b0, b1);
            mma_f16(s4[1][1], a1, b2, b3);
            LDSM4(b0, b1, b2, b3, aK + koff + 16 * APH * 2);
            mma_f16(s4[0][2], a0, b0, b1);
            mma_f16(s4[0][3], a0, b2, b3);
            mma_f16(s4[1][2], a1, b0, b1);
            mma_f16(s4[1][3], a1, b2, b3);
        }
        #pragma unroll
        for (int mf = 0; mf < 2; mf++) {
            #pragma unroll
            for (int ni = 0; ni < 4; ni++) {
                const int col = n0 + ni * 8 + 2 * tg;
                const int kj0 = k0 + col;
                #pragma unroll
                for (int rr = 0; rr < 2; rr++) {
                    const int row = m0 + mf * 16 + rr * 8 + g;
                    const int qi = q0 + row;
                    const bool ok0 = (kj0 <= qi) && (qi - kj0 < WIN);
                    const bool ok1 = (kj0 + 1 <= qi) && (qi - kj0 - 1 < WIN);
                    Ps[row * APS + col]     = ok0 ? s4[mf][ni][rr * 2 + 0] : -1e30f;
                    Ps[row * APS + col + 1] = ok1 ? s4[mf][ni][rr * 2 + 1] : -1e30f;
                }
            }
        }
        __syncthreads();

        {
            float pm = -1e30f;
            #pragma unroll
            for (int jj = 0; jj < 32; jj++)
                pm = fmaxf(pm, Ps[i_row * APS + grp * 32 + jj]);
            red[i_row * 2 + grp] = pm;
        }
        __syncthreads();
        if (t < QT) {
            const float mo = row_m[t];
            float mx = fmaxf(fmaxf(red[t * 2 + 0], red[t * 2 + 1]), mo);
            row_a[t] = expf(mo - mx);
            row_m[t] = mx;
        }
        __syncthreads();
        {
            const float m = row_m[i_row];
            float psum = 0.f;
            #pragma unroll
            for (int jj = 0; jj < 32; jj++) {
                const float sv = Ps[i_row * APS + grp * 32 + jj];
                const float p = (sv > -1e29f) ? expf(sv - m) : 0.f;
                Ph[i_row * APH + grp * 32 + jj] = __float2half_rn(p);
                psum += p;
            }
            red[i_row * 2 + grp] = psum;
        }
        __syncthreads();
        if (t < QT)
            row_l[t] = row_l[t] * row_a[t] + red[t * 2 + 0] + red[t * 2 + 1];

        #pragma unroll
        for (int mf = 0; mf < 2; mf++) {
            const float al0 = row_a[m0 + mf * 16 + g];
            const float al1 = row_a[m0 + mf * 16 + 8 + g];
            #pragma unroll
            for (int ni = 0; ni < 4; ni++) {
                o[mf][ni][0] *= al0; o[mf][ni][1] *= al0;
                o[mf][ni][2] *= al1; o[mf][ni][3] *= al1;
            }
        }

        #pragma unroll
        for (int kk = 0; kk < 4; kk++) {
            const uint32_t koff = kk * 32;
            uint32_t a0[4], a1[4];
            LDSM4(a0[0], a0[1], a0[2], a0[3], aP + koff);
            LDSM4(a1[0], a1[1], a1[2], a1[3], aP + koff + 16 * APH * 2);
            uint32_t b0, b1, b2, b3;
            LDSM4(b0, b1, b2, b3, aV + koff);
            mma_f16(o[0][0], a0, b0, b1);
            mma_f16(o[0][1], a0, b2, b3);
            mma_f16(o[1][0], a1, b0, b1);
            mma_f16(o[1][1], a1, b2, b3);
            LDSM4(b0, b1, b2, b3, aV + koff + 16 * APH * 2);
            mma_f16(o[0][2], a0, b0, b1);
            mma_f16(o[0][3], a0, b2, b3);
            mma_f16(o[1][2], a1, b0, b1);
            mma_f16(o[1][3], a1, b2, b3);
        }
    }

    __syncthreads();
    #pragma unroll
    for (int mf = 0; mf < 2; mf++) {
        const float inv0 = 1.f / row_l[m0 + mf * 16 + g];
        const float inv1 = 1.f / row_l[m0 + mf * 16 + 8 + g];
        const size_t r0 = (size_t)(b * 1024 + q0 + m0 + mf * 16 + g) * 1024;
        const size_t r1 = r0 + 8 * 1024;
        #pragma unroll
        for (int ni = 0; ni < 4; ni++) {
            const int col = h * 64 + n0 + ni * 8 + 2 * tg;
            *(__half2*)(ctxh + r0 + col) =
                __floats2half2_rn(o[mf][ni][0] * inv0, o[mf][ni][1] * inv0);
            *(__half2*)(ctxh + r1 + col) =
                __floats2half2_rn(o[mf][ni][2] * inv1, o[mf][ni][3] * inv1);
        }
    }
}

// ---------------------------------------------------------------------------
// LayerNorm: optional second fp16 output
// ---------------------------------------------------------------------------
__global__ void __launch_bounds__(256) ln_kernel(
    const float* __restrict__ in, const float* __restrict__ g,
    const float* __restrict__ be, float* __restrict__ out,
    __half* __restrict__ outh)
{
    __shared__ float red[8];
    __shared__ float s_mu, s_rs;
    const int t = threadIdx.x;
    const size_t row = blockIdx.x;

    float4 v = ((const float4*)(in + row * 1024))[t];
    float sum = v.x + v.y + v.z + v.w;
    #pragma unroll
    for (int o = 16; o; o >>= 1) sum += __shfl_xor_sync(~0u, sum, o);
    if ((t & 31) == 0) red[t >> 5] = sum;
    __syncthreads();
    if (t == 0) {
        float s = 0.f;
        #pragma unroll
        for (int i = 0; i < 8; i++) s += red[i];
        s_mu = s * (1.f / 1024.f);
    }
    __syncthreads();
    const float mu = s_mu;
    const float dx = v.x - mu, dy = v.y - mu, dz = v.z - mu, dw = v.w - mu;
    float sq = dx * dx + dy * dy + dz * dz + dw * dw;
    #pragma unroll
    for (int o = 16; o; o >>= 1) sq += __shfl_xor_sync(~0u, sq, o);
    __syncthreads();
    if ((t & 31) == 0) red[t >> 5] = sq;
    __syncthreads();
    if (t == 0) {
        float s = 0.f;
        #pragma unroll
        for (int i = 0; i < 8; i++) s += red[i];
        s_rs = rsqrtf(s * (1.f / 1024.f) + 1e-5f);
    }
    __syncthreads();
    const float rs = s_rs;
    float4 gv = ((const float4*)g)[t];
    float4 bv = ((const float4*)be)[t];
    float4 o;
    o.x = dx * rs * gv.x + bv.x;
    o.y = dy * rs * gv.y + bv.y;
    o.z = dz * rs * gv.z + bv.z;
    o.w = dw * rs * gv.w + bv.w;
    ((float4*)(out + row * 1024))[t] = o;
    if (outh) {
        __half2* oh = (__half2*)(outh + row * 1024);
        oh[t * 2 + 0] = __floats2half2_rn(o.x, o.y);
        oh[t * 2 + 1] = __floats2half2_rn(o.z, o.w);
    }
}

// ---------------------------------------------------------------------------
// launch
// ---------------------------------------------------------------------------
extern "C" void kernel_launch(void* const* d_in, const int* in_sizes, int n_in,
                              void* d_out, int out_size)
{
    const float* x    = (const float*)d_in[0];
    const float* Wqkv = (const float*)d_in[1];
    const float* bqkv = (const float*)d_in[2];
    const float* Wo   = (const float*)d_in[3];
    const float* bo   = (const float*)d_in[4];
    const float* W1   = (const float*)d_in[5];
    const float* b1   = (const float*)d_in[6];
    const float* W2   = (const float*)d_in[7];
    const float* b2   = (const float*)d_in[8];
    const float* g1   = (const float*)d_in[9];
    const float* be1  = (const float*)d_in[10];
    const float* g2   = (const float*)d_in[11];
    const float* be2  = (const float*)d_in[12];
    float* out = (float*)d_out;

    float *y, *x1;
    __half *qkvh, *xh, *ctxh, *x1h, *hh, *wqkvh, *woh, *w1h, *w2h;
    cudaGetSymbolAddress((void**)&y,     g_y);
    cudaGetSymbolAddress((void**)&x1,    g_x1);
    cudaGetSymbolAddress((void**)&qkvh,  g_qkvh);
    cudaGetSymbolAddress((void**)&xh,    g_xh);
    cudaGetSymbolAddress((void**)&ctxh,  g_ctxh);
    cudaGetSymbolAddress((void**)&x1h,   g_x1h);
    cudaGetSymbolAddress((void**)&hh,    g_hh);
    cudaGetSymbolAddress((void**)&wqkvh, g_wqkvh);
    cudaGetSymbolAddress((void**)&woh,   g_woh);
    cudaGetSymbolAddress((void**)&w1h,   g_w1h);
    cudaGetSymbolAddress((void**)&w2h,   g_w2h);

    cudaFuncSetAttribute(attn_kernel,
                         cudaFuncAttributeMaxDynamicSharedMemorySize, ATTN_SMEM);
    cudaFuncSetAttribute((hgemm<false, false, true, 1024>),
                         cudaFuncAttributeMaxDynamicSharedMemorySize, GEMM_SMEM);
    cudaFuncSetAttribute((hgemm<false, true, false, 1024>),
                         cudaFuncAttributeMaxDynamicSharedMemorySize, GEMM_SMEM);
    cudaFuncSetAttribute((hgemm<true, false, true, 1024>),
                         cudaFuncAttributeMaxDynamicSharedMemorySize, GEMM_SMEM);
    cudaFuncSetAttribute((hgemm<false, true, false, 4096>),
                         cudaFuncAttributeMaxDynamicSharedMemorySize, GEMM_SMEM);

    dim3 thr(256);

    // 0) convert x + 4 weights to fp16 (single fused launch)
    cvt_all_kernel<<<2048, thr>>>(
        (const float4*)x,    (__half2*)xh,    TOKENS * CDIM / 4,
        (const float4*)Wqkv, (__half2*)wqkvh, 3 * CDIM * CDIM / 4,
        (const float4*)Wo,   (__half2*)woh,   CDIM * CDIM / 4,
        (const float4*)W1,   (__half2*)w1h,   FFDIM * CDIM / 4,
        (const float4*)W2,   (__half2*)w2h,   CDIM * FFDIM / 4);

    // 1) QKV projection -> fp16 qkv
    hgemm<false, false, true, 1024><<<dim3(3072 / GBN, TOKENS / GBM), thr, GEMM_SMEM>>>(
        xh, wqkvh, bqkv, nullptr, qkvh, 3 * CDIM);
    // 2) banded attention (fp16 MMA, q-tile 128) -> fp16 ctx
    attn_kernel<<<dim3(1024 / QT, 4 * 16), thr, ATTN_SMEM>>>(qkvh, ctxh);
    // 3) Wo + bias + residual(x exact) -> y fp32
    hgemm<false, true, false, 1024><<<dim3(CDIM / GBN, TOKENS / GBM), thr, GEMM_SMEM>>>(
        ctxh, woh, bo, x, y, CDIM);
    // 4) LN1 -> x1 (fp32 exact) + x1h (fp16)
    ln_kernel<<<TOKENS, thr>>>(y, g1, be1, x1, x1h);
    // 5) W1 + bias + GELU -> hh fp16
    hgemm<true, false, true, 1024><<<dim3(FFDIM / GBN, TOKENS / GBM), thr, GEMM_SMEM>>>(
        x1h, w1h, b1, nullptr, hh, FFDIM);
    // 6) W2 + bias + residual(x1 exact) -> y fp32
    hgemm<false, true, false, 4096><<<dim3(CDIM / GBN, TOKENS / GBM), thr, GEMM_SMEM>>>(
        hh, w2h, b2, x1, y, CDIM);
    // 7) LN2 -> out
    ln_kernel<<<TOKENS, thr>>>(y, g2, be2, out, nullptr);
}

// round 17
// speedup vs baseline: 1.0954x; 1.0954x over previous
#include <cuda_runtime.h>
#include <cuda_fp16.h>
#include <math.h>
#include <stdint.h>

// ---------------------------------------------------------------------------
// Problem: B=4, T=1024, C=1024, H=16, Dh=64, D_FF=4096, WINDOW=256. M=4096.
// ---------------------------------------------------------------------------
#define TOKENS 4096
#define CDIM   1024
#define FFDIM  4096
#define WIN    256

__device__ float  g_y[TOKENS * CDIM];
__device__ float  g_x1[TOKENS * CDIM];         // exact (residual)
__device__ __half g_qkvh[TOKENS * 3 * CDIM];   // fp16 qkv
__device__ __half g_xh[TOKENS * CDIM];
__device__ __half g_ctxh[TOKENS * CDIM];
__device__ __half g_x1h[TOKENS * CDIM];
__device__ __half g_hh[TOKENS * FFDIM];
__device__ __half g_wqkvh[3 * CDIM * CDIM];
__device__ __half g_woh[CDIM * CDIM];
__device__ __half g_w1h[FFDIM * CDIM];
__device__ __half g_w2h[CDIM * FFDIM];

// ---------------------------------------------------------------------------
// helpers
// ---------------------------------------------------------------------------
__device__ __forceinline__ uint32_t smem_u32(const void* p) {
    uint32_t a;
    asm("{ .reg .u64 t; cvta.to.shared.u64 t, %1; cvt.u32.u64 %0, t; }"
        : "=r"(a) : "l"(p));
    return a;
}

#define CP_ASYNC16(sa, ga) \
    asm volatile("cp.async.cg.shared.global [%0], [%1], 16;" :: "r"((uint32_t)(sa)), "l"(ga))
#define CP_COMMIT() asm volatile("cp.async.commit_group;" ::: "memory")
#define CP_WAIT(n)  asm volatile("cp.async.wait_group %0;" :: "n"(n) : "memory")

#define LDSM4(R0, R1, R2, R3, ADDR) \
    asm volatile("ldmatrix.sync.aligned.m8n8.x4.shared.b16 {%0,%1,%2,%3}, [%4];" \
        : "=r"(R0), "=r"(R1), "=r"(R2), "=r"(R3) : "r"(ADDR))

__device__ __forceinline__ void mma_f16(float* d, const uint32_t* a,
                                        uint32_t b0, uint32_t b1) {
    asm volatile(
        "mma.sync.aligned.m16n8k16.row.col.f32.f16.f16.f32 "
        "{%0,%1,%2,%3}, {%4,%5,%6,%7}, {%8,%9}, {%0,%1,%2,%3};"
        : "+f"(d[0]), "+f"(d[1]), "+f"(d[2]), "+f"(d[3])
        : "r"(a[0]), "r"(a[1]), "r"(a[2]), "r"(a[3]), "r"(b0), "r"(b1));
}

__device__ __forceinline__ float gelu_exact(float v) {
    return 0.5f * v * (1.0f + erff(v * 0.70710678118654752f));
}

// ---------------------------------------------------------------------------
// fused fp32 -> fp16 conversion pass over 5 buffers (sizes in float4 units)
// ---------------------------------------------------------------------------
__global__ void __launch_bounds__(256) cvt_all_kernel(
    const float4* __restrict__ i0, __half2* __restrict__ o0, int n0,
    const float4* __restrict__ i1, __half2* __restrict__ o1, int n1,
    const float4* __restrict__ i2, __half2* __restrict__ o2, int n2,
    const float4* __restrict__ i3, __half2* __restrict__ o3, int n3,
    const float4* __restrict__ i4, __half2* __restrict__ o4, int n4)
{
    const int total = n0 + n1 + n2 + n3 + n4;
    const int stride = gridDim.x * 256;
    for (int i = blockIdx.x * 256 + threadIdx.x; i < total; i += stride) {
        const float4* src;
        __half2* dst;
        int idx = i;
        if (idx < n0)                    { src = i0; dst = o0; }
        else if ((idx -= n0) < n1)       { src = i1; dst = o1; }
        else if ((idx -= n1) < n2)       { src = i2; dst = o2; }
        else if ((idx -= n2) < n3)       { src = i3; dst = o3; }
        else            { idx -= n3;       src = i4; dst = o4; }
        float4 v = src[idx];
        dst[2 * idx + 0] = __floats2half2_rn(v.x, v.y);
        dst[2 * idx + 1] = __floats2half2_rn(v.z, v.w);
    }
}

// ---------------------------------------------------------------------------
// fp16 mma.sync GEMM — EXACT R11/R15 config (confirmed plateau across 5
// structural variants; do not touch).
// CTA 128x128xBK64, 8 warps (4m x 2n), warp tile 32x64, 2-stage cp.async.
// ---------------------------------------------------------------------------
#define GBM 128
#define GBN 128
#define GBK 64
#define HSTR 72
#define HSTG ((GBM + GBN) * HSTR)
#define GEMM_SMEM (2 * HSTG * 2)           // 73728 bytes

template <bool GELU, bool RESID, bool OUTH, int KDIM>
__global__ void __launch_bounds__(256, 2) hgemm(
    const __half* __restrict__ A, const __half* __restrict__ B,
    const float* __restrict__ bias, const float* __restrict__ resid,
    void* __restrict__ Cv, int N)
{
    extern __shared__ __half smh[];
    const int tid  = threadIdx.x;
    const int wid  = tid >> 5, lane = tid & 31;
    const int wm   = wid >> 1, wn = wid & 1;
    const int g    = lane >> 2, tg = lane & 3;
    const int m0   = blockIdx.y * GBM;
    const int n0   = blockIdx.x * GBN;
    constexpr int NITER = KDIM / GBK;
    static_assert(NITER % 2 == 0, "NITER even");

    float acc[2][8][4];
    #pragma unroll
    for (int i = 0; i < 2; i++)
        #pragma unroll
        for (int j = 0; j < 8; j++)
            #pragma unroll
            for (int k = 0; k < 4; k++) acc[i][j][k] = 0.f;

    const int lr = tid >> 3;
    const int ls = (tid & 7) * 8;
    const __half* aptr = A + (size_t)(m0 + lr) * KDIM + ls;
    const __half* bptr = B + (size_t)(n0 + lr) * KDIM + ls;
    const uint32_t sa_st = smem_u32(smh) + (uint32_t)(lr * HSTR + ls) * 2u;
    const uint32_t sb_st = sa_st + GBM * HSTR * 2u;
    constexpr uint32_t STGB = HSTG * 2u;

    auto load_chunk = [&](uint32_t stoff) {
        #pragma unroll
        for (int i = 0; i < 4; i++)
            CP_ASYNC16(sa_st + stoff + i * (32 * HSTR * 2),
                       aptr + (size_t)i * 32 * KDIM);
        #pragma unroll
        for (int i = 0; i < 4; i++)
            CP_ASYNC16(sb_st + stoff + i * (32 * HSTR * 2),
                       bptr + (size_t)i * 32 * KDIM);
        aptr += GBK; bptr += GBK;
    };

    const uint32_t smb = smem_u32(smh);
    const int m_a = wm * 32 + ((lane >> 3) & 1) * 8 + (lane & 7);
    const uint32_t aAb = smb + (uint32_t)(m_a * HSTR + (lane >> 4) * 8) * 2u;
    const int n_b = wn * 64 + (lane >> 4) * 8 + (lane & 7);
    const uint32_t aBb = smb + (uint32_t)(GBM * HSTR + n_b * HSTR
                                          + ((lane >> 3) & 1) * 8) * 2u;

    auto compute = [&](uint32_t stoff) {
        #pragma unroll
        for (int kk = 0; kk < GBK / 16; kk++) {
            const uint32_t koff = stoff + kk * 32;
            uint32_t a[2][4];
            LDSM4(a[0][0], a[0][1], a[0][2], a[0][3], aAb + koff);
            LDSM4(a[1][0], a[1][1], a[1][2], a[1][3],
                  aAb + koff + 16 * HSTR * 2);
            #pragma unroll
            for (int p = 0; p < 4; p++) {
                uint32_t b0, b1, b2, b3;
                LDSM4(b0, b1, b2, b3, aBb + koff + p * (16 * HSTR * 2));
                mma_f16(acc[0][2 * p],     a[0], b0, b1);
                mma_f16(acc[1][2 * p],     a[1], b0, b1);
                mma_f16(acc[0][2 * p + 1], a[0], b2, b3);
                mma_f16(acc[1][2 * p + 1], a[1], b2, b3);
            }
        }
    };

    load_chunk(0); CP_COMMIT();

    #pragma unroll 1
    for (int j = 0; j < NITER; j += 2) {
        load_chunk(STGB); CP_COMMIT();
        CP_WAIT(1);
        __syncthreads();
        compute(0);
        __syncthreads();
        if (j + 2 < NITER) load_chunk(0);
        CP_COMMIT();
        CP_WAIT(1);
        __syncthreads();
        compute(STGB);
        __syncthreads();
    }

    #pragma unroll
    for (int mi = 0; mi < 2; mi++) {
        #pragma unroll
        for (int rr = 0; rr < 2; rr++) {
            const int m = m0 + wm * 32 + mi * 16 + rr * 8 + g;
            const float* rrow = RESID ? (resid + (size_t)m * N) : nullptr;
            #pragma unroll
            for (int ni = 0; ni < 8; ni++) {
                const int n = n0 + wn * 64 + ni * 8 + 2 * tg;
                float ox = acc[mi][ni][rr * 2 + 0] + bias[n];
                float oy = acc[mi][ni][rr * 2 + 1] + bias[n + 1];
                if (RESID) { ox += rrow[n]; oy += rrow[n + 1]; }
                if (GELU)  { ox = gelu_exact(ox); oy = gelu_exact(oy); }
                if (OUTH) {
                    __half* crow = (__half*)Cv + (size_t)m * N;
                    *(__half2*)(crow + n) = __floats2half2_rn(ox, oy);
                } else {
                    float* crow = (float*)Cv + (size_t)m * N;
                    *(float2*)(crow + n) = make_float2(ox, oy);
                }
            }
        }
    }
}

// ---------------------------------------------------------------------------
// Banded causal attention, fp16 mma.sync, q-tile 128, REGISTER softmax:
// S stays in accumulator regs; mask/max/exp in regs; cross-warp row stats
// via 2-slot smem combine (redm/reds). Ps fp32 buffer eliminated; 4 barriers
// per k-tile (was 5). row_a eliminated (alpha lives in regs).
// ---------------------------------------------------------------------------
#define QT  128
#define APH 72
// halves: Qh(128) + Kh(64) + Vt(64) + Ph(128) rows x APH; floats: row_m/row_l
// (2*QT) + redm/reds (4*QT)
#define ATTN_SMEM ((2 * QT + 2 * 64) * APH * 2 + (2 * QT + 4 * QT) * 4)

__global__ void __launch_bounds__(256, 2) attn_kernel(
    const __half* __restrict__ qkv, __half* __restrict__ ctxh)
{
    extern __shared__ __half smh[];
    __half* Qh = smh;                       // 128 x APH
    __half* Kh = smh + QT * APH;            // 64 x APH
    __half* Vt = Kh + 64 * APH;             // 64 x APH  ([d][k])
    __half* Ph = Vt + 64 * APH;             // 128 x APH
    float* row_m = (float*)(Ph + QT * APH); // 128
    float* row_l = row_m + QT;              // 128
    float* redm  = row_l + QT;              // 128 x 2
    float* reds  = redm + 2 * QT;           // 128 x 2

    const int t    = threadIdx.x;
    const int wid  = t >> 5, lane = t & 31;
    const int g    = lane >> 2, tg = lane & 3;
    const int wm   = wid >> 1, wn = wid & 1;
    const int m0   = wm * 32;
    const int n0   = wn * 32;
    const int bh   = blockIdx.y;
    const int b    = bh >> 4, h = bh & 15;
    const int q0   = blockIdx.x * QT;
    const size_t base = (size_t)b * 1024 * 3072 + (size_t)h * 64;

    // load + scale Q: 128 rows, 2 threads per row x 32 halves
    {
        const int r = t >> 1, c = (t & 1) * 32;
        const __half2 sc = __floats2half2_rn(0.125f, 0.125f);
        #pragma unroll
        for (int cc = 0; cc < 32; cc += 8) {
            uint4 v = *(const uint4*)(qkv + base + (size_t)(q0 + r) * 3072 + c + cc);
            __half2* hv = (__half2*)&v;
            hv[0] = __hmul2(hv[0], sc); hv[1] = __hmul2(hv[1], sc);
            hv[2] = __hmul2(hv[2], sc); hv[3] = __hmul2(hv[3], sc);
            *(uint4*)&Qh[r * APH + c + cc] = v;
        }
    }
    if (t < QT) { row_m[t] = -1e30f; row_l[t] = 0.f; }

    float o[2][4][4];
    #pragma unroll
    for (int mf = 0; mf < 2; mf++)
        #pragma unroll
        for (int i = 0; i < 4; i++)
            #pragma unroll
            for (int j = 0; j < 4; j++) o[mf][i][j] = 0.f;

    const uint32_t smb = smem_u32(smh);
    const int m_a = m0 + ((lane >> 3) & 1) * 8 + (lane & 7);
    const uint32_t kofA = (lane >> 4) * 8;
    const uint32_t aQ = smb + (uint32_t)(m_a * APH + kofA) * 2u;
    const uint32_t aP = aQ + (uint32_t)((QT + 2 * 64) * APH) * 2u;
    const int n_b = n0 + (lane >> 4) * 8 + (lane & 7);
    const uint32_t kofB = ((lane >> 3) & 1) * 8;
    const uint32_t aK = smb + (uint32_t)(QT * APH + n_b * APH + kofB) * 2u;
    const uint32_t aV = aK + (uint32_t)(64 * APH) * 2u;

    const int kt_lo = (q0 >= WIN) ? ((q0 - (WIN - 1)) >> 6) : 0;
    const int kt_hi = (q0 + QT - 1) >> 6;

    const int lrow = t >> 2;            // K/V loader: 0..63
    const int lcol = (t & 3) * 16;

    for (int kt = kt_lo; kt <= kt_hi; kt++) {
        const int k0 = kt * 64;
        __syncthreads();   // prior reads of Kh/Vt done; Qh published (1st iter)
        {
            #pragma unroll
            for (int cc = 0; cc < 16; cc += 8) {
                uint4 kv = *(const uint4*)(qkv + base + (size_t)(k0 + lrow) * 3072 + 1024 + lcol + cc);
                *(uint4*)&Kh[lrow * APH + lcol + cc] = kv;
                uint4 vv = *(const uint4*)(qkv + base + (size_t)(k0 + lrow) * 3072 + 2048 + lcol + cc);
                const __half* hv = (const __half*)&vv;
                #pragma unroll
                for (int i = 0; i < 8; i++)
                    Vt[(lcol + cc + i) * APH + lrow] = hv[i];
            }
        }
        __syncthreads();

        // S = Q K^T  (warp tile m32 x n32), kept in registers
        float s4[2][4][4];
        #pragma unroll
        for (int mf = 0; mf < 2; mf++)
            #pragma unroll
            for (int i = 0; i < 4; i++)
                #pragma unroll
                for (int j = 0; j < 4; j++) s4[mf][i][j] = 0.f;
        #pragma unroll
        for (int kk = 0; kk < 4; kk++) {
            const uint32_t koff = kk * 32;
            uint32_t a0[4], a1[4];
            LDSM4(a0[0], a0[1], a0[2], a0[3], aQ + koff);
            LDSM4(a1[0], a1[1], a1[2], a1[3], aQ + koff + 16 * APH * 2);
            uint32_t b0, b1, b2, b3;
            LDSM4(b0, b1, b2, b3, aK + koff);
            mma_f16(s4[0][0], a0, b0, b1);
            mma_f16(s4[0][1], a0, b2, b3);
            mma_f16(s4[1][0], a1, b0, b1);
            mma_f16(s4[1][1], a1, b2, b3);
            LDSM4(b0, b1, b2, b3, aK + koff + 16 * APH * 2);
            mma_f16(s4[0][2], a0, b0, b1);
            mma_f16(s4[0][3], a0, b2, b3);
            mma_f16(s4[1][2], a1, b0, b1);
            mma_f16(s4[1][3], a1, b2, b3);
        }

        // mask in regs + per-row warp max via quad shuffles
        #pragma unroll
        for (int mf = 0; mf < 2; mf++) {
            #pragma unroll
            for (int rr = 0; rr < 2; rr++) {
                const int row = m0 + mf * 16 + rr * 8 + g;
                const int qi  = q0 + row;
                float pm = -1e30f;
                #pragma unroll
                for (int ni = 0; ni < 4; ni++) {
                    const int kj0 = k0 + n0 + ni * 8 + 2 * tg;
                    if (!((kj0 <= qi) && (qi - kj0 < WIN)))
                        s4[mf][ni][rr * 2 + 0] = -1e30f;
                    if (!((kj0 + 1 <= qi) && (qi - kj0 - 1 < WIN)))
                        s4[mf][ni][rr * 2 + 1] = -1e30f;
                    pm = fmaxf(pm, fmaxf(s4[mf][ni][rr * 2 + 0],
                                         s4[mf][ni][rr * 2 + 1]));
                }
                pm = fmaxf(pm, __shfl_xor_sync(~0u, pm, 1));
                pm = fmaxf(pm, __shfl_xor_sync(~0u, pm, 2));
                if (tg == 0) redm[row * 2 + wn] = pm;
            }
        }
        __syncthreads();

        // combine row stats (old row_m read here; written only post next barrier)
        float mx[2][2], al[2][2];
        #pragma unroll
        for (int mf = 0; mf < 2; mf++)
            #pragma unroll
            for (int rr = 0; rr < 2; rr++) {
                const int row = m0 + mf * 16 + rr * 8 + g;
                const float mo = row_m[row];
                const float m = fmaxf(fmaxf(redm[row * 2], redm[row * 2 + 1]), mo);
                mx[mf][rr] = m;
                al[mf][rr] = expf(mo - m);
            }

        // exp in regs -> Ph fp16 + per-row partial sums
        #pragma unroll
        for (int mf = 0; mf < 2; mf++) {
            #pragma unroll
            for (int rr = 0; rr < 2; rr++) {
                const int row = m0 + mf * 16 + rr * 8 + g;
                float rs = 0.f;
                #pragma unroll
                for (int ni = 0; ni < 4; ni++) {
                    const int col = n0 + ni * 8 + 2 * tg;
                    const float s0 = s4[mf][ni][rr * 2 + 0];
                    const float s1 = s4[mf][ni][rr * 2 + 1];
                    const float p0 = (s0 > -1e29f) ? expf(s0 - mx[mf][rr]) : 0.f;
                    const float p1 = (s1 > -1e29f) ? expf(s1 - mx[mf][rr]) : 0.f;
                    *(__half2*)&Ph[row * APH + col] = __floats2half2_rn(p0, p1);
                    rs += p0 + p1;
                }
                rs += __shfl_xor_sync(~0u, rs, 1);
                rs += __shfl_xor_sync(~0u, rs, 2);
                if (tg == 0) reds[row * 2 + wn] = rs;
            }
        }
        __syncthreads();

        // designated owners update shared row stats (read next tile only)
        if (wn == 0 && tg == 0) {
            #pragma unroll
            for (int mf = 0; mf < 2; mf++)
                #pragma unroll
                for (int rr = 0; rr < 2; rr++) {
                    const int row = m0 + mf * 16 + rr * 8 + g;
                    row_l[row] = row_l[row] * al[mf][rr]
                               + reds[row * 2] + reds[row * 2 + 1];
                    row_m[row] = mx[mf][rr];
                }
        }

        // rescale accumulators (alpha in registers)
        #pragma unroll
        for (int mf = 0; mf < 2; mf++)
            #pragma unroll
            for (int ni = 0; ni < 4; ni++) {
                o[mf][ni][0] *= al[mf][0]; o[mf][ni][1] *= al[mf][0];
                o[mf][ni][2] *= al[mf][1]; o[mf][ni][3] *= al[mf][1];
            }

        // O += P V
        #pragma unroll
        for (int kk = 0; kk < 4; kk++) {
            const uint32_t koff = kk * 32;
            uint32_t a0[4], a1[4];
            LDSM4(a0[0], a0[1], a0[2], a0[3], aP + koff);
            LDSM4(a1[0], a1[1], a1[2], a1[3], aP + koff + 16 * APH * 2);
            uint32_t b0, b1, b2, b3;
            LDSM4(b0, b1, b2, b3, aV + koff);
            mma_f16(o[0][0], a0, b0, b1);
            mma_f16(o[0][1], a0, b2, b3);
            mma_f16(o[1][0], a1, b0, b1);
            mma_f16(o[1][1], a1, b2, b3);
            LDSM4(b0, b1, b2, b3, aV + koff + 16 * APH * 2);
            mma_f16(o[0][2], a0, b0, b1);
            mma_f16(o[0][3], a0, b2, b3);
            mma_f16(o[1][2], a1, b0, b1);
            mma_f16(o[1][3], a1, b2, b3);
        }
    }

    __syncthreads();   // row_l final
    #pragma unroll
    for (int mf = 0; mf < 2; mf++) {
        const float inv0 = 1.f / row_l[m0 + mf * 16 + g];
        const float inv1 = 1.f / row_l[m0 + mf * 16 + 8 + g];
        const size_t r0 = (size_t)(b * 1024 + q0 + m0 + mf * 16 + g) * 1024;
        const size_t r1 = r0 + 8 * 1024;
        #pragma unroll
        for (int ni = 0; ni < 4; ni++) {
            const int col = h * 64 + n0 + ni * 8 + 2 * tg;
            *(__half2*)(ctxh + r0 + col) =
                __floats2half2_rn(o[mf][ni][0] * inv0, o[mf][ni][1] * inv0);
            *(__half2*)(ctxh + r1 + col) =
                __floats2half2_rn(o[mf][ni][2] * inv1, o[mf][ni][3] * inv1);
        }
    }
}

// ---------------------------------------------------------------------------
// LayerNorm: optional second fp16 output
// ---------------------------------------------------------------------------
__global__ void __launch_bounds__(256) ln_kernel(
    const float* __restrict__ in, const float* __restrict__ g,
    const float* __restrict__ be, float* __restrict__ out,
    __half* __restrict__ outh)
{
    __shared__ float red[8];
    __shared__ float s_mu, s_rs;
    const int t = threadIdx.x;
    const size_t row = blockIdx.x;

    float4 v = ((const float4*)(in + row * 1024))[t];
    float sum = v.x + v.y + v.z + v.w;
    #pragma unroll
    for (int o = 16; o; o >>= 1) sum += __shfl_xor_sync(~0u, sum, o);
    if ((t & 31) == 0) red[t >> 5] = sum;
    __syncthreads();
    if (t == 0) {
        float s = 0.f;
        #pragma unroll
        for (int i = 0; i < 8; i++) s += red[i];
        s_mu = s * (1.f / 1024.f);
    }
    __syncthreads();
    const float mu = s_mu;
    const float dx = v.x - mu, dy = v.y - mu, dz = v.z - mu, dw = v.w - mu;
    float sq = dx * dx + dy * dy + dz * dz + dw * dw;
    #pragma unroll
    for (int o = 16; o; o >>= 1) sq += __shfl_xor_sync(~0u, sq, o);
    __syncthreads();
    if ((t & 31) == 0) red[t >> 5] = sq;
    __syncthreads();
    if (t == 0) {
        float s = 0.f;
        #pragma unroll
        for (int i = 0; i < 8; i++) s += red[i];
        s_rs = rsqrtf(s * (1.f / 1024.f) + 1e-5f);
    }
    __syncthreads();
    const float rs = s_rs;
    float4 gv = ((const float4*)g)[t];
    float4 bv = ((const float4*)be)[t];
    float4 o;
    o.x = dx * rs * gv.x + bv.x;
    o.y = dy * rs * gv.y + bv.y;
    o.z = dz * rs * gv.z + bv.z;
    o.w = dw * rs * gv.w + bv.w;
    ((float4*)(out + row * 1024))[t] = o;
    if (outh) {
        __half2* oh = (__half2*)(outh + row * 1024);
        oh[t * 2 + 0] = __floats2half2_rn(o.x, o.y);
        oh[t * 2 + 1] = __floats2half2_rn(o.z, o.w);
    }
}

// ---------------------------------------------------------------------------
// launch
// ---------------------------------------------------------------------------
extern "C" void kernel_launch(void* const* d_in, const int* in_sizes, int n_in,
                              void* d_out, int out_size)
{
    const float* x    = (const float*)d_in[0];
    const float* Wqkv = (const float*)d_in[1];
    const float* bqkv = (const float*)d_in[2];
    const float* Wo   = (const float*)d_in[3];
    const float* bo   = (const float*)d_in[4];
    const float* W1   = (const float*)d_in[5];
    const float* b1   = (const float*)d_in[6];
    const float* W2   = (const float*)d_in[7];
    const float* b2   = (const float*)d_in[8];
    const float* g1   = (const float*)d_in[9];
    const float* be1  = (const float*)d_in[10];
    const float* g2   = (const float*)d_in[11];
    const float* be2  = (const float*)d_in[12];
    float* out = (float*)d_out;

    float *y, *x1;
    __half *qkvh, *xh, *ctxh, *x1h, *hh, *wqkvh, *woh, *w1h, *w2h;
    cudaGetSymbolAddress((void**)&y,     g_y);
    cudaGetSymbolAddress((void**)&x1,    g_x1);
    cudaGetSymbolAddress((void**)&qkvh,  g_qkvh);
    cudaGetSymbolAddress((void**)&xh,    g_xh);
    cudaGetSymbolAddress((void**)&ctxh,  g_ctxh);
    cudaGetSymbolAddress((void**)&x1h,   g_x1h);
    cudaGetSymbolAddress((void**)&hh,    g_hh);
    cudaGetSymbolAddress((void**)&wqkvh, g_wqkvh);
    cudaGetSymbolAddress((void**)&woh,   g_woh);
    cudaGetSymbolAddress((void**)&w1h,   g_w1h);
    cudaGetSymbolAddress((void**)&w2h,   g_w2h);

    cudaFuncSetAttribute(attn_kernel,
                         cudaFuncAttributeMaxDynamicSharedMemorySize, ATTN_SMEM);
    cudaFuncSetAttribute((hgemm<false, false, true, 1024>),
                         cudaFuncAttributeMaxDynamicSharedMemorySize, GEMM_SMEM);
    cudaFuncSetAttribute((hgemm<false, true, false, 1024>),
                         cudaFuncAttributeMaxDynamicSharedMemorySize, GEMM_SMEM);
    cudaFuncSetAttribute((hgemm<true, false, true, 1024>),
                         cudaFuncAttributeMaxDynamicSharedMemorySize, GEMM_SMEM);
    cudaFuncSetAttribute((hgemm<false, true, false, 4096>),
                         cudaFuncAttributeMaxDynamicSharedMemorySize, GEMM_SMEM);

    dim3 thr(256);

    // 0) convert x + 4 weights to fp16 (single fused launch)
    cvt_all_kernel<<<2048, thr>>>(
        (const float4*)x,    (__half2*)xh,    TOKENS * CDIM / 4,
        (const float4*)Wqkv, (__half2*)wqkvh, 3 * CDIM * CDIM / 4,
        (const float4*)Wo,   (__half2*)woh,   CDIM * CDIM / 4,
        (const float4*)W1,   (__half2*)w1h,   FFDIM * CDIM / 4,
        (const float4*)W2,   (__half2*)w2h,   CDIM * FFDIM / 4);

    // 1) QKV projection -> fp16 qkv
    hgemm<false, false, true, 1024><<<dim3(3072 / GBN, TOKENS / GBM), thr, GEMM_SMEM>>>(
        xh, wqkvh, bqkv, nullptr, qkvh, 3 * CDIM);
    // 2) banded attention (fp16 MMA, q-tile 128, register softmax) -> fp16 ctx
    attn_kernel<<<dim3(1024 / QT, 4 * 16), thr, ATTN_SMEM>>>(qkvh, ctxh);
    // 3) Wo + bias + residual(x exact) -> y fp32
    hgemm<false, true, false, 1024><<<dim3(CDIM / GBN, TOKENS / GBM), thr, GEMM_SMEM>>>(
        ctxh, woh, bo, x, y, CDIM);
    // 4) LN1 -> x1 (fp32 exact) + x1h (fp16)
    ln_kernel<<<TOKENS, thr>>>(y, g1, be1, x1, x1h);
    // 5) W1 + bias + GELU -> hh fp16
    hgemm<true, false, true, 1024><<<dim3(FFDIM / GBN, TOKENS / GBM), thr, GEMM_SMEM>>>(
        x1h, w1h, b1, nullptr, hh, FFDIM);
    // 6) W2 + bias + residual(x1 exact) -> y fp32
    hgemm<false, true, false, 4096><<<dim3(CDIM / GBN, TOKENS / GBM), thr, GEMM_SMEM>>>(
        hh, w2h, b2, x1, y, CDIM);
    // 7) LN2 -> out
    ln_kernel<<<TOKENS, thr>>>(y, g2, be2, out, nullptr);
}